// round 13
// baseline (speedup 1.0000x reference)
#include <cuda_runtime.h>
#include <math.h>
#include <stdint.h>

#define Bb   2
#define Nn   4096
#define GNNc 64
#define LATc 128
#define KG   12
#define KP   8
#define Mm   32768
#define BN   (Bb*Nn)
#define BM   (Bb*Mm)
#define GPP  16
#define NT   4
#define PROJ_GRID (BM/GPP/NT)   // 1024

typedef unsigned long long ull;

__device__ float g_x  [BN*GNNc];
__device__ float g_v  [BN*GNNc];
__device__ float g_o  [BN*GNNc];
__device__ float g_pf [BN*LATc];
__device__ int   g_nbr[BN*KG];
__device__ int   g_gidx[BM*KP];
__device__ float g_gd2 [BM*KP];
__device__ float g_chsumP[128*256];
__device__ float g_s[2*GNNc];

__device__ __forceinline__ float gelu_f(float x){
    return 0.5f * x * (1.0f + erff(x * 0.7071067811865476f));
}
__device__ __forceinline__ float sqsum_A(float x, float y, float z){
    return __fadd_rn(__fadd_rn(__fmul_rn(x,x), __fmul_rn(y,y)), __fmul_rn(z,z));
}
__device__ __forceinline__ float grid_coord(int i){
    return (float)(-1.0 + (2.0/31.0) * (double)i);
}

// lexicographic (d, idx) insert — order-independent, matches stable top_k exactly
template<int KK>
__device__ __forceinline__ void lex_insert(float (&kd)[KK], int (&ki)[KK], float d, int j){
    if ((d < kd[KK-1]) || (d == kd[KK-1] && j < ki[KK-1])){
        kd[KK-1] = d; ki[KK-1] = j;
        #pragma unroll
        for (int r=KK-1; r>0; r--){
            if ((kd[r] < kd[r-1]) || (kd[r] == kd[r-1] && ki[r] < ki[r-1])){
                float td=kd[r]; kd[r]=kd[r-1]; kd[r-1]=td;
                int   ti=ki[r]; ki[r]=ki[r-1]; ki[r-1]=ti;
            }
        }
    }
}

// min-extraction batch insert: insert only successive argmins while they qualify
template<int KK>
__device__ __forceinline__ void batch_insert8(float (&kd)[KK], int (&ki)[KK],
                                              float e0,float e1,float e2,float e3,
                                              float e4,float e5,float e6,float e7,
                                              int jb){
    float mn = fminf(fminf(fminf(e0,e1),fminf(e2,e3)),
                     fminf(fminf(e4,e5),fminf(e6,e7)));
    if (mn <= kd[KK-1]){
        float dd8[8] = {e0,e1,e2,e3,e4,e5,e6,e7};
        while (true){
            float dm = dd8[0]; int im = 0;
            #pragma unroll
            for (int i=1;i<8;i++) if (dd8[i] < dm){ dm = dd8[i]; im = i; }
            int jm = jb + im;
            if ((dm < kd[KK-1]) || (dm == kd[KK-1] && jm < ki[KK-1])){
                kd[KK-1] = dm; ki[KK-1] = jm;
                #pragma unroll
                for (int r=KK-1; r>0; r--){
                    if ((kd[r] < kd[r-1]) || (kd[r] == kd[r-1] && ki[r] < ki[r-1])){
                        float td=kd[r]; kd[r]=kd[r-1]; kd[r-1]=td;
                        int   ti=ki[r]; ki[r]=ki[r-1]; ki[r-1]=ti;
                    }
                }
                #pragma unroll
                for (int i=0;i<8;i++) if (i == im) dd8[i] = 3.5e38f;
            } else break;
        }
    }
}

// ---- packed f32x2 helpers -------------------------------------------------------
__device__ __forceinline__ ull pk2(float a, float b){
    ull r;
    asm("mov.b64 %0, {%1, %2};" : "=l"(r) : "r"(__float_as_uint(a)), "r"(__float_as_uint(b)));
    return r;
}
__device__ __forceinline__ ull ffma2(ull a, ull b, ull c){
    ull d;
    asm("fma.rn.f32x2 %0, %1, %2, %3;" : "=l"(d) : "l"(a), "l"(b), "l"(c));
    return d;
}
__device__ __forceinline__ ull fmul2(ull a, ull b){
    ull d;
    asm("mul.rn.f32x2 %0, %1, %2;" : "=l"(d) : "l"(a), "l"(b));
    return d;
}
__device__ __forceinline__ ull fadd2(ull a, ull b){
    ull d;
    asm("add.rn.f32x2 %0, %1, %2;" : "=l"(d) : "l"(a), "l"(b));
    return d;
}
__device__ __forceinline__ float2 upk2(ull a){
    unsigned int lo, hi;
    asm("mov.b64 {%0, %1}, %2;" : "=r"(lo), "=r"(hi) : "l"(a));
    float2 f; f.x = __uint_as_float(lo); f.y = __uint_as_float(hi);
    return f;
}
__device__ __forceinline__ ull d2_pair(ull ppx, ull ppy, ull ppz, ull pp2, ull n2,
                                       ull xx, ull yy, ull zz, ull ww){
    ull dot = fmul2(ppx, xx);
    dot = ffma2(ppy, yy, dot);
    dot = ffma2(ppz, zz, dot);
    return ffma2(n2, dot, fadd2(pp2, ww));
}

// ---------------- k_input (+ chsum zeroing) -------------------------------------
__global__ void k_input(const float* __restrict__ feats,
                        const float* __restrict__ W,
                        const float* __restrict__ bias){
    if (blockIdx.x == 0 && threadIdx.x < 128) g_chsumP[threadIdx.x*256] = 0.0f;
    int t = blockIdx.x*blockDim.x + threadIdx.x;
    if (t >= BN*GNNc) return;
    int row = t >> 6, c = t & 63;
    const float* f = feats + row*9;
    float acc = bias[c];
    #pragma unroll
    for (int j=0;j<9;j++) acc = fmaf(f[j], W[j*GNNc + c], acc);
    g_x[t] = acc;
}

// --------- packed candidate builder: P1=(x0,x1,y0,y1) P2=(z0,z1,w0,w1) ----------
__device__ __forceinline__ void build_packed(const float* __restrict__ cb,
                                             float4* P1, float4* P2, int tid, int nthr){
    for (int p = tid; p < 2048; p += nthr){
        int j = p*2;
        float x0=cb[j*3  ], y0=cb[j*3+1], z0=cb[j*3+2];
        float x1=cb[j*3+3], y1=cb[j*3+4], z1=cb[j*3+5];
        P1[p] = make_float4(x0,x1,y0,y1);
        P2[p] = make_float4(z0,z1, sqsum_A(x0,y0,z0), sqsum_A(x1,y1,z1));
    }
}

// ---------------- self kNN: lane=query, 8-way candidate split, 512 thr ----------
#define SELF_MERGE_N (2*7*32*KG)
#define SELF_SMEM (Nn*16 + SELF_MERGE_N*8)
__global__ void __launch_bounds__(512) k_knn_self(const float* __restrict__ coords){
    extern __shared__ float4 sp[];
    float4* P1 = sp;
    float4* P2 = sp + 2048;
    float*  mD = (float*)(sp + 4096);
    int*    mI = (int*)(mD + SELF_MERGE_N);
    int tid = threadIdx.x, wid = tid>>5, lane = tid&31;
    int qg = wid & 1, sub = wid >> 1;
    int q = blockIdx.x*64 + qg*32 + lane;
    int b  = q / Nn;
    int il = q % Nn;
    const float* cb = coords + b*Nn*3;
    build_packed(cb, P1, P2, tid, 512);
    __syncthreads();
    float px = cb[il*3], py = cb[il*3+1], pz = cb[il*3+2];
    float pp = sqsum_A(px,py,pz);
    ull ppx=pk2(px,px), ppy=pk2(py,py), ppz=pk2(pz,pz), pp2=pk2(pp,pp);
    ull n2 = pk2(-2.0f,-2.0f);
    float kd[KG]; int ki[KG];
    #pragma unroll
    for (int r=0;r<KG;r++){ kd[r]=3.4e38f; ki[r]=0; }
    const ulonglong2* U1 = (const ulonglong2*)P1;
    const ulonglong2* U2 = (const ulonglong2*)P2;
    int p0 = sub*256;
    for (int p=p0; p<p0+256; p+=4){
        ulonglong2 u1a=U1[p],   u2a=U2[p];
        ulonglong2 u1b=U1[p+1], u2b=U2[p+1];
        ulonglong2 u1c=U1[p+2], u2c=U2[p+2];
        ulonglong2 u1d=U1[p+3], u2d=U2[p+3];
        float2 da = upk2(d2_pair(ppx,ppy,ppz,pp2,n2, u1a.x,u1a.y,u2a.x,u2a.y));
        float2 db = upk2(d2_pair(ppx,ppy,ppz,pp2,n2, u1b.x,u1b.y,u2b.x,u2b.y));
        float2 dc = upk2(d2_pair(ppx,ppy,ppz,pp2,n2, u1c.x,u1c.y,u2c.x,u2c.y));
        float2 dd = upk2(d2_pair(ppx,ppy,ppz,pp2,n2, u1d.x,u1d.y,u2d.x,u2d.y));
        int j = p*2;
        if (j   == il) da.x = 3.5e38f;
        if (j+1 == il) da.y = 3.5e38f;
        if (j+2 == il) db.x = 3.5e38f;
        if (j+3 == il) db.y = 3.5e38f;
        if (j+4 == il) dc.x = 3.5e38f;
        if (j+5 == il) dc.y = 3.5e38f;
        if (j+6 == il) dd.x = 3.5e38f;
        if (j+7 == il) dd.y = 3.5e38f;
        batch_insert8(kd,ki, da.x,da.y,db.x,db.y,dc.x,dc.y,dd.x,dd.y, j);
    }
    if (sub){
        int base = ((qg*7 + sub-1)*32 + lane)*KG;
        #pragma unroll
        for (int r=0;r<KG;r++){ mD[base+r]=kd[r]; mI[base+r]=ki[r]; }
    }
    __syncthreads();
    if (!sub){
        for (int s=0; s<7; s++){
            int base = ((qg*7 + s)*32 + lane)*KG;
            #pragma unroll
            for (int r=0;r<KG;r++) lex_insert(kd,ki, mD[base+r], mI[base+r]);
        }
        #pragma unroll
        for (int r=0;r<KG;r++) g_nbr[q*KG + r] = ki[r];
    }
}

// ---------------- grid kNN: 4 subs x 128 queries, 512 thr, 512 blocks -----------
#define GRID_SMEM (Nn*16)
__global__ void __launch_bounds__(512) k_knn_grid(const float* __restrict__ coords){
    extern __shared__ float4 sp[];
    float4* P1 = sp;
    float4* P2 = sp + 2048;
    int tid = threadIdx.x, wid = tid>>5, lane = tid&31;
    int sub = wid >> 2;                  // 0..3
    int ql  = (wid & 3)*32 + lane;       // 0..127
    int q = blockIdx.x*128 + ql;
    int b = q / Mm;
    int m = q % Mm;
    const float* cb = coords + b*Nn*3;
    build_packed(cb, P1, P2, tid, 512);
    __syncthreads();
    float px = grid_coord( m        & 31);
    float py = grid_coord((m >> 5)  & 31);
    float pz = grid_coord( m >> 10      );
    float pp = sqsum_A(px,py,pz);
    ull ppx=pk2(px,px), ppy=pk2(py,py), ppz=pk2(pz,pz), pp2=pk2(pp,pp);
    ull n2 = pk2(-2.0f,-2.0f);
    float kd[KP]; int ki[KP];
    #pragma unroll
    for (int r=0;r<KP;r++){ kd[r]=3.4e38f; ki[r]=0; }
    const ulonglong2* U1 = (const ulonglong2*)P1;
    const ulonglong2* U2 = (const ulonglong2*)P2;
    int p0 = sub*512;
    for (int p=p0; p<p0+512; p+=4){
        ulonglong2 u1a=U1[p],   u2a=U2[p];
        ulonglong2 u1b=U1[p+1], u2b=U2[p+1];
        ulonglong2 u1c=U1[p+2], u2c=U2[p+2];
        ulonglong2 u1d=U1[p+3], u2d=U2[p+3];
        float2 da = upk2(d2_pair(ppx,ppy,ppz,pp2,n2, u1a.x,u1a.y,u2a.x,u2a.y));
        float2 db = upk2(d2_pair(ppx,ppy,ppz,pp2,n2, u1b.x,u1b.y,u2b.x,u2b.y));
        float2 dc = upk2(d2_pair(ppx,ppy,ppz,pp2,n2, u1c.x,u1c.y,u2c.x,u2c.y));
        float2 dd = upk2(d2_pair(ppx,ppy,ppz,pp2,n2, u1d.x,u1d.y,u2d.x,u2d.y));
        batch_insert8(kd,ki, da.x,da.y,db.x,db.y,dc.x,dc.y,dd.x,dd.y, p*2);
    }
    __syncthreads();                       // scan done -> safe to reuse smem
    float* mD = (float*)sp;
    int*   mI = (int*)(mD + 3*128*KP);
    if (sub){
        int base = ((sub-1)*128 + ql)*KP;
        #pragma unroll
        for (int r=0;r<KP;r++){ mD[base+r]=kd[r]; mI[base+r]=ki[r]; }
    }
    __syncthreads();
    if (!sub){
        for (int s=0; s<3; s++){
            int base = (s*128 + ql)*KP;
            #pragma unroll
            for (int r=0;r<KP;r++) lex_insert(kd,ki, mD[base+r], mI[base+r]);
        }
        #pragma unroll
        for (int r=0;r<KP;r++){
            g_gidx[q*KP + r] = ki[r];
            g_gd2 [q*KP + r] = kd[r];
        }
    }
}

// ---------------- row GEMM ------------------------------------------------------
template<int OUT>
__global__ void k_rowgemm(const float* __restrict__ X,
                          const float* __restrict__ W,
                          const float* __restrict__ bias,
                          float* __restrict__ Y){
    __shared__ float Ws[64*OUT];
    __shared__ float xs[8][64];
    int tid = threadIdx.x;
    for (int t=tid; t<64*OUT; t+=256) Ws[t]=W[t];
    int w = tid>>5, l = tid&31;
    int r0 = blockIdx.x*8;
    for (int t=tid; t<512; t+=256) xs[t>>6][t&63] = X[(r0 + (t>>6))*64 + (t&63)];
    __syncthreads();
    int r = r0 + w;
    float acc[OUT/32];
    #pragma unroll
    for (int i=0;i<OUT/32;i++) acc[i] = bias[l + i*32];
    #pragma unroll 8
    for (int j=0;j<64;j++){
        float xj = xs[w][j];
        #pragma unroll
        for (int i=0;i<OUT/32;i++) acc[i] = fmaf(xj, Ws[j*OUT + l + i*32], acc[i]);
    }
    #pragma unroll
    for (int i=0;i<OUT/32;i++) Y[r*OUT + l + i*32] = acc[i];
}

// ---------------- GNO message passing -------------------------------------------
__global__ void k_gno_out(const float* __restrict__ coords,
                          const float* __restrict__ kW1, const float* __restrict__ kb1,
                          const float* __restrict__ kW2, const float* __restrict__ kb2,
                          int layer){
    __shared__ float W1s[96], b1s[32], W2s[32*64], b2s[64];
    __shared__ float gsh[4][KG*32];
    __shared__ float relb[4][KG][3];
    __shared__ int   ji[4][KG];
    __shared__ float psum[256];
    int tid = threadIdx.x;
    int p = tid>>6, c = tid&63;
    int pt0 = blockIdx.x*4;
    for (int t=tid; t<2048; t+=256) W2s[t]=kW2[t];
    if (tid < 96) W1s[tid]=kW1[tid];
    else if (tid < 128) b1s[tid-96]=kb1[tid-96];
    else if (tid < 192) b2s[tid-128]=kb2[tid-128];
    if (tid < 4*KG){
        int pl = tid/KG, k = tid%KG;
        int gp = pt0 + pl;
        int b = gp/Nn, i = gp%Nn;
        const float* cb = coords + b*Nn*3;
        int j = g_nbr[gp*KG + k];
        ji[pl][k] = j;
        relb[pl][k][0] = cb[j*3]  -cb[i*3];
        relb[pl][k][1] = cb[j*3+1]-cb[i*3+1];
        relb[pl][k][2] = cb[j*3+2]-cb[i*3+2];
    }
    __syncthreads();
    for (int t=tid; t<4*KG*32; t+=256){
        int pl = t/384; int rem = t - pl*384;
        int k = rem>>5, h = rem&31;
        float d = fmaf(relb[pl][k][2], W1s[64+h],
                  fmaf(relb[pl][k][1], W1s[32+h],
                  fmaf(relb[pl][k][0], W1s[h], b1s[h])));
        gsh[pl][rem] = gelu_f(d);
    }
    __syncthreads();
    int gp = pt0 + p;
    int b = gp/Nn;
    float outc = 0.0f, b2c = b2s[c];
    #pragma unroll
    for (int k=0;k<KG;k++){
        float vn = g_v[(b*Nn + ji[p][k])*GNNc + c];
        float s = b2c;
        #pragma unroll
        for (int h=0;h<32;h++) s = fmaf(gsh[p][k*32+h], W2s[h*64+c], s);
        outc = fmaf(s, vn, outc);
    }
    g_o[gp*GNNc + c] = outc;
    psum[tid] = outc;
    __syncthreads();
    if (tid < 64){
        float s = psum[tid]+psum[tid+64]+psum[tid+128]+psum[tid+192];
        atomicAdd(&g_chsumP[(layer*64 + tid)*256], s);
    }
}

__global__ void k_se(const float* __restrict__ seW1, const float* __restrict__ seW2,
                     int layer){
    __shared__ float ms[64], hs[16];
    int c = threadIdx.x;
    ms[c] = g_chsumP[(layer*64 + c)*256] * (1.0f/(float)BN);
    __syncthreads();
    if (c < 16){
        float a=0.f;
        #pragma unroll
        for (int j=0;j<64;j++) a = fmaf(ms[j], seW1[j*16+c], a);
        hs[c] = gelu_f(a);
    }
    __syncthreads();
    float a=0.f;
    #pragma unroll
    for (int h=0;h<16;h++) a = fmaf(hs[h], seW2[h*64+c], a);
    g_s[layer*64 + c] = 1.0f/(1.0f + expf(-a));
}

__global__ void k_gno_ln(const float* __restrict__ lng, const float* __restrict__ lnb,
                         int layer){
    int tid = threadIdx.x;
    int w = tid>>5, l = tid&31;
    int r = blockIdx.x*8 + w;
    float s0 = g_s[layer*64 + l], s1 = g_s[layer*64 + l+32];
    float y0 = gelu_f(fmaf(g_o[r*64+l],    s0, g_v[r*64+l]));
    float y1 = gelu_f(fmaf(g_o[r*64+l+32], s1, g_v[r*64+l+32]));
    float t1 = y0+y1, t2 = y0*y0 + y1*y1;
    #pragma unroll
    for (int off=16; off>0; off>>=1){
        t1 += __shfl_xor_sync(0xffffffffu, t1, off);
        t2 += __shfl_xor_sync(0xffffffffu, t2, off);
    }
    float mean = t1*(1.0f/64.0f);
    float var  = t2*(1.0f/64.0f) - mean*mean;
    float rs   = rsqrtf(var + 1e-5f);
    g_x[r*64+l]    = (y0-mean)*rs*lng[l]    + lnb[l];
    g_x[r*64+l+32] = (y1-mean)*rs*lng[l+32] + lnb[l+32];
}

// ============ projection v3: fp32 FFMA2 (unchanged) =============================
#define PF_W2   0
#define PF_HS   16384
#define PF_W1   20480
#define PF_B1   20864
#define PF_B2   20992
#define PF_LG   21120
#define PF_LB   21248
#define PF_REL  21376
#define PF_WR   21760
#define PF_JI   21888
#define PROJ_FLOATS 22016
#define PROJ_SMEM (PROJ_FLOATS*4)
#define JC 32

__global__ void __launch_bounds__(256,2)
k_proj_v3(const float* __restrict__ coords,
          const float* __restrict__ W1, const float* __restrict__ b1,
          const float* __restrict__ W2, const float* __restrict__ b2,
          const float* __restrict__ lng, const float* __restrict__ lnb,
          float* __restrict__ out){
    extern __shared__ float sh[];
    float* W2s = sh + PF_W2;
    ull* hs = (ull*)(sh + PF_HS);
    float* W1s = sh + PF_W1;
    float* b1s = sh + PF_B1;
    float* b2s = sh + PF_B2;
    float* lgs = sh + PF_LG;
    float* lbs = sh + PF_LB;
    float* relb= sh + PF_REL;
    float* wrs = sh + PF_WR;
    int*   jis = (int*)(sh + PF_JI);

    int tid = threadIdx.x, wid = tid>>5, l = tid&31;

    for (int i=tid; i<4096; i+=256) ((float4*)W2s)[i] = ((const float4*)W2)[i];
    for (int t=tid; t<384; t+=256) W1s[t]=W1[t];
    if (tid < 128){ b1s[tid]=b1[tid]; lgs[tid]=lng[tid]; }
    else { b2s[tid-128]=b2[tid-128]; lbs[tid-128]=lnb[tid-128]; }
    if (tid < 128){ b2s[tid]=b2[tid]; lbs[tid]=lnb[tid]; }
    else { b1s[tid-128]=b1[tid-128]; lgs[tid-128]=lng[tid-128]; }

    for (int tile=0; tile<NT; tile++){
        int gt = blockIdx.x*NT + tile;
        int base = gt * GPP;
        int b  = base / Mm;
        int m0 = base % Mm;
        const float* cb = coords + b*Nn*3;

        if (tid < 128){
            int gih = tid>>3, k = tid&7;
            int m = m0 + gih;
            float px = grid_coord( m        & 31);
            float py = grid_coord((m >> 5)  & 31);
            float pz = grid_coord( m >> 10      );
            long qk = (long)(b*Mm + m)*KP + k;
            int id  = g_gidx[qk];
            float d2 = g_gd2[qk];
            float dist = sqrtf(fmaxf(d2, 1e-12f));
            wrs[tid] = 1.0f/(dist + 1e-6f);
            jis[tid] = id;
            relb[tid*3+0] = px - cb[id*3];
            relb[tid*3+1] = py - cb[id*3+1];
            relb[tid*3+2] = pz - cb[id*3+2];
        }
        __syncthreads();

        ull acc[8][4];
        #pragma unroll
        for (int p=0;p<8;p++){ acc[p][0]=0; acc[p][1]=0; acc[p][2]=0; acc[p][3]=0; }
        int p0 = wid*8;

        int gp2  = tid>>2;
        int r0g = 2*gp2, r1g = 2*gp2+1;
        float a0=relb[r0g*3], a1=relb[r0g*3+1], a2=relb[r0g*3+2];
        float c0=relb[r1g*3], c1=relb[r1g*3+1], c2=relb[r1g*3+2];
        int joct = (tid&3)*8;

        for (int jc=0; jc<128; jc+=JC){
            #pragma unroll
            for (int u=0; u<8; u++){
                int j = jc + joct + u;
                float h0 = gelu_f(fmaf(a2, W1s[256+j], fmaf(a1, W1s[128+j], fmaf(a0, W1s[j], b1s[j]))));
                float h1 = gelu_f(fmaf(c2, W1s[256+j], fmaf(c1, W1s[128+j], fmaf(c0, W1s[j], b1s[j]))));
                hs[gp2*JC + joct + u] = pk2(h0, h1);
            }
            __syncthreads();
            #pragma unroll 4
            for (int jj=0; jj<JC; jj++){
                int j = jc + jj;
                float4 w4 = ((float4*)(W2s + j*128))[l];
                ull wx = pk2(w4.x, w4.x);
                ull wy = pk2(w4.y, w4.y);
                ull wz = pk2(w4.z, w4.z);
                ull ww = pk2(w4.w, w4.w);
                #pragma unroll
                for (int p=0;p<8;p++){
                    ull h = hs[(p0+p)*JC + jj];
                    acc[p][0] = ffma2(h, wx, acc[p][0]);
                    acc[p][1] = ffma2(h, wy, acc[p][1]);
                    acc[p][2] = ffma2(h, wz, acc[p][2]);
                    acc[p][3] = ffma2(h, ww, acc[p][3]);
                }
            }
            __syncthreads();
        }

        float4 b2v = ((float4*)b2s)[l];
        float og[2][4] = {{0,0,0,0},{0,0,0,0}};
        #pragma unroll
        for (int p=0;p<8;p++){
            int r0 = wid*16 + 2*p, r1 = r0+1;
            int g = p>>2;
            float w0 = wrs[r0], w1 = wrs[r1];
            const float* pfr0 = g_pf + (long)(b*Nn + jis[r0])*LATc + 4*l;
            const float* pfr1 = g_pf + (long)(b*Nn + jis[r1])*LATc + 4*l;
            float4 pf0 = *(const float4*)pfr0;
            float4 pf1 = *(const float4*)pfr1;
            float2 v0 = upk2(acc[p][0]);
            float2 v1 = upk2(acc[p][1]);
            float2 v2 = upk2(acc[p][2]);
            float2 v3 = upk2(acc[p][3]);
            og[g][0] = fmaf((v0.x+b2v.x)*w0, pf0.x, fmaf((v0.y+b2v.x)*w1, pf1.x, og[g][0]));
            og[g][1] = fmaf((v1.x+b2v.y)*w0, pf0.y, fmaf((v1.y+b2v.y)*w1, pf1.y, og[g][1]));
            og[g][2] = fmaf((v2.x+b2v.z)*w0, pf0.z, fmaf((v2.y+b2v.z)*w1, pf1.z, og[g][2]));
            og[g][3] = fmaf((v3.x+b2v.w)*w0, pf0.w, fmaf((v3.y+b2v.w)*w1, pf1.w, og[g][3]));
        }

        #pragma unroll
        for (int g=0; g<2; g++){
            int gi = 2*wid + g;
            float ws = 0.f;
            #pragma unroll
            for (int k=0;k<KP;k++) ws += wrs[gi*8+k];
            float inv = 1.0f/ws;
            float o0 = og[g][0]*inv, o1 = og[g][1]*inv, o2 = og[g][2]*inv, o3 = og[g][3]*inv;
            float s1 = o0+o1+o2+o3;
            float s2 = o0*o0+o1*o1+o2*o2+o3*o3;
            #pragma unroll
            for (int off=16; off>0; off>>=1){
                s1 += __shfl_xor_sync(0xffffffffu, s1, off);
                s2 += __shfl_xor_sync(0xffffffffu, s2, off);
            }
            float mean = s1*(1.0f/128.0f);
            float var  = s2*(1.0f/128.0f) - mean*mean;
            float rs   = rsqrtf(var + 1e-5f);
            long obase = ((long)b*128)*Mm + m0 + gi;
            int c = 4*l;
            out[obase + (long)(c  )*Mm] = (o0-mean)*rs*lgs[c  ] + lbs[c  ];
            out[obase + (long)(c+1)*Mm] = (o1-mean)*rs*lgs[c+1] + lbs[c+1];
            out[obase + (long)(c+2)*Mm] = (o2-mean)*rs*lgs[c+2] + lbs[c+2];
            out[obase + (long)(c+3)*Mm] = (o3-mean)*rs*lgs[c+3] + lbs[c+3];
        }
        __syncthreads();
    }
}

// ---------------- launcher -------------------------------------------------------
extern "C" void kernel_launch(void* const* d_in, const int* in_sizes, int n_in,
                              void* d_out, int out_size){
    const float* coords = (const float*)d_in[0];
    const float* feats  = (const float*)d_in[1];
    const float* W_in   = (const float*)d_in[2];
    const float* b_in   = (const float*)d_in[3];
    const float* W_lat  = (const float*)d_in[24];
    const float* b_lat  = (const float*)d_in[25];
    const float* p_kW1  = (const float*)d_in[26];
    const float* p_kb1  = (const float*)d_in[27];
    const float* p_kW2  = (const float*)d_in[28];
    const float* p_kb2  = (const float*)d_in[29];
    const float* p_lng  = (const float*)d_in[30];
    const float* p_lnb  = (const float*)d_in[31];

    cudaFuncSetAttribute(k_knn_self, cudaFuncAttributeMaxDynamicSharedMemorySize, SELF_SMEM);
    cudaFuncSetAttribute(k_knn_grid, cudaFuncAttributeMaxDynamicSharedMemorySize, GRID_SMEM);
    cudaFuncSetAttribute(k_proj_v3,  cudaFuncAttributeMaxDynamicSharedMemorySize, PROJ_SMEM);

    float* xg; cudaGetSymbolAddress((void**)&xg, g_x);
    float* vg; cudaGetSymbolAddress((void**)&vg, g_v);
    float* pfg; cudaGetSymbolAddress((void**)&pfg, g_pf);

    // slot 4 of ncu sampling = k_knn_grid (measure min-extraction version)
    k_input<<<(BN*GNNc)/256, 256>>>(feats, W_in, b_in);
    k_knn_self<<<BN/64, 512, SELF_SMEM>>>(coords);
    k_rowgemm<64><<<BN/8, 256>>>(xg, (const float*)d_in[8], (const float*)d_in[9], vg);
    k_knn_grid<<<BM/128, 512, GRID_SMEM>>>(coords);

    for (int layer = 0; layer < 2; layer++){
        int base = 4 + layer*10;
        const float* kW1  = (const float*)d_in[base+0];
        const float* kb1  = (const float*)d_in[base+1];
        const float* kW2  = (const float*)d_in[base+2];
        const float* kb2  = (const float*)d_in[base+3];
        const float* vW   = (const float*)d_in[base+4];
        const float* vb   = (const float*)d_in[base+5];
        const float* lng  = (const float*)d_in[base+6];
        const float* lnb  = (const float*)d_in[base+7];
        const float* seW1 = (const float*)d_in[base+8];
        const float* seW2 = (const float*)d_in[base+9];

        if (layer == 1)
            k_rowgemm<64><<<BN/8, 256>>>(xg, vW, vb, vg);
        k_gno_out<<<BN/4, 256>>>(coords, kW1, kb1, kW2, kb2, layer);
        k_se<<<1, 64>>>(seW1, seW2, layer);
        k_gno_ln<<<BN/8, 256>>>(lng, lnb, layer);
    }

    k_rowgemm<128><<<BN/8, 256>>>(xg, W_lat, b_lat, pfg);
    k_proj_v3<<<PROJ_GRID, 256, PROJ_SMEM>>>(coords, p_kW1, p_kb1, p_kW2, p_kb2,
                                             p_lng, p_lnb, (float*)d_out);
}

// round 14
// speedup vs baseline: 1.1989x; 1.1989x over previous
#include <cuda_runtime.h>
#include <math.h>
#include <stdint.h>

#define Bb   2
#define Nn   4096
#define GNNc 64
#define LATc 128
#define KG   12
#define KP   8
#define Mm   32768
#define BN   (Bb*Nn)
#define BM   (Bb*Mm)
#define GPP  16
#define NT   4
#define PROJ_GRID (BM/GPP/NT)   // 1024

typedef unsigned long long ull;

__device__ float g_x  [BN*GNNc];
__device__ float g_v  [BN*GNNc];
__device__ float g_o  [BN*GNNc];
__device__ float g_pf [BN*LATc];
__device__ int   g_nbr[BN*KG];
__device__ int   g_gidx[BM*KP];
__device__ float g_gd2 [BM*KP];
__device__ float g_chsumP[128*256];
__device__ float g_s[2*GNNc];

__device__ __forceinline__ float gelu_f(float x){
    return 0.5f * x * (1.0f + erff(x * 0.7071067811865476f));
}
__device__ __forceinline__ float sqsum_A(float x, float y, float z){
    return __fadd_rn(__fadd_rn(__fmul_rn(x,x), __fmul_rn(y,y)), __fmul_rn(z,z));
}
__device__ __forceinline__ float grid_coord(int i){
    return (float)(-1.0 + (2.0/31.0) * (double)i);
}
template<int KK>
__device__ __forceinline__ void knn_insert(float (&kd)[KK], int (&ki)[KK], float d2, int j){
    if (d2 < kd[KK-1]){
        kd[KK-1] = d2; ki[KK-1] = j;
        #pragma unroll
        for (int r=KK-1; r>0; r--){
            if (kd[r] < kd[r-1]){
                float td=kd[r]; kd[r]=kd[r-1]; kd[r-1]=td;
                int   ti=ki[r]; ki[r]=ki[r-1]; ki[r-1]=ti;
            }
        }
    }
}

// ---- packed f32x2 helpers (probe-verified; per-lane rounding == scalar) --------
__device__ __forceinline__ ull pk2(float a, float b){
    ull r;
    asm("mov.b64 %0, {%1, %2};" : "=l"(r) : "r"(__float_as_uint(a)), "r"(__float_as_uint(b)));
    return r;
}
__device__ __forceinline__ ull ffma2(ull a, ull b, ull c){
    ull d;
    asm("fma.rn.f32x2 %0, %1, %2, %3;" : "=l"(d) : "l"(a), "l"(b), "l"(c));
    return d;
}
__device__ __forceinline__ ull fmul2(ull a, ull b){
    ull d;
    asm("mul.rn.f32x2 %0, %1, %2;" : "=l"(d) : "l"(a), "l"(b));
    return d;
}
__device__ __forceinline__ ull fadd2(ull a, ull b){
    ull d;
    asm("add.rn.f32x2 %0, %1, %2;" : "=l"(d) : "l"(a), "l"(b));
    return d;
}
__device__ __forceinline__ float2 upk2(ull a){
    unsigned int lo, hi;
    asm("mov.b64 {%0, %1}, %2;" : "=r"(lo), "=r"(hi) : "l"(a));
    float2 f; f.x = __uint_as_float(lo); f.y = __uint_as_float(hi);
    return f;
}
__device__ __forceinline__ ull d2_pair(ull ppx, ull ppy, ull ppz, ull pp2, ull n2,
                                       ull xx, ull yy, ull zz, ull ww){
    ull dot = fmul2(ppx, xx);
    dot = ffma2(ppy, yy, dot);
    dot = ffma2(ppz, zz, dot);
    return ffma2(n2, dot, fadd2(pp2, ww));
}

// ---------------- k_input (+ chsum zeroing) -------------------------------------
__global__ void k_input(const float* __restrict__ feats,
                        const float* __restrict__ W,
                        const float* __restrict__ bias){
    if (blockIdx.x == 0 && threadIdx.x < 128) g_chsumP[threadIdx.x*256] = 0.0f;
    int t = blockIdx.x*blockDim.x + threadIdx.x;
    if (t >= BN*GNNc) return;
    int row = t >> 6, c = t & 63;
    const float* f = feats + row*9;
    float acc = bias[c];
    #pragma unroll
    for (int j=0;j<9;j++) acc = fmaf(f[j], W[j*GNNc + c], acc);
    g_x[t] = acc;
}

// --------- packed candidate builder: P1=(x0,x1,y0,y1) P2=(z0,z1,w0,w1) ----------
__device__ __forceinline__ void build_packed(const float* __restrict__ cb,
                                             float4* P1, float4* P2, int tid, int nthr){
    for (int p = tid; p < 2048; p += nthr){
        int j = p*2;
        float x0=cb[j*3  ], y0=cb[j*3+1], z0=cb[j*3+2];
        float x1=cb[j*3+3], y1=cb[j*3+4], z1=cb[j*3+5];
        P1[p] = make_float4(x0,x1,y0,y1);
        P2[p] = make_float4(z0,z1, sqsum_A(x0,y0,z0), sqsum_A(x1,y1,z1));
    }
}

// ---------------- self kNN: lane=query, 8-way candidate split, 512 thr ----------
#define SELF_MERGE_N (2*7*32*KG)
#define SELF_SMEM (Nn*16 + SELF_MERGE_N*8)
__global__ void __launch_bounds__(512) k_knn_self(const float* __restrict__ coords){
    extern __shared__ float4 sp[];
    float4* P1 = sp;
    float4* P2 = sp + 2048;
    float*  mD = (float*)(sp + 4096);
    int*    mI = (int*)(mD + SELF_MERGE_N);
    int tid = threadIdx.x, wid = tid>>5, lane = tid&31;
    int qg = wid & 1, sub = wid >> 1;
    int q = blockIdx.x*64 + qg*32 + lane;
    int b  = q / Nn;
    int il = q % Nn;
    const float* cb = coords + b*Nn*3;
    build_packed(cb, P1, P2, tid, 512);
    __syncthreads();
    float px = cb[il*3], py = cb[il*3+1], pz = cb[il*3+2];
    float pp = sqsum_A(px,py,pz);
    ull ppx=pk2(px,px), ppy=pk2(py,py), ppz=pk2(pz,pz), pp2=pk2(pp,pp);
    ull n2 = pk2(-2.0f,-2.0f);
    float kd[KG]; int ki[KG];
    #pragma unroll
    for (int r=0;r<KG;r++){ kd[r]=3.4e38f; ki[r]=0; }
    const ulonglong2* U1 = (const ulonglong2*)P1;
    const ulonglong2* U2 = (const ulonglong2*)P2;
    int p0 = sub*256;
    for (int p=p0; p<p0+256; p+=4){
        ulonglong2 u1a=U1[p],   u2a=U2[p];
        ulonglong2 u1b=U1[p+1], u2b=U2[p+1];
        ulonglong2 u1c=U1[p+2], u2c=U2[p+2];
        ulonglong2 u1d=U1[p+3], u2d=U2[p+3];
        float2 da = upk2(d2_pair(ppx,ppy,ppz,pp2,n2, u1a.x,u1a.y,u2a.x,u2a.y));
        float2 db = upk2(d2_pair(ppx,ppy,ppz,pp2,n2, u1b.x,u1b.y,u2b.x,u2b.y));
        float2 dc = upk2(d2_pair(ppx,ppy,ppz,pp2,n2, u1c.x,u1c.y,u2c.x,u2c.y));
        float2 dd = upk2(d2_pair(ppx,ppy,ppz,pp2,n2, u1d.x,u1d.y,u2d.x,u2d.y));
        int j = p*2;
        if (j   == il) da.x = 3.5e38f;
        if (j+1 == il) da.y = 3.5e38f;
        if (j+2 == il) db.x = 3.5e38f;
        if (j+3 == il) db.y = 3.5e38f;
        if (j+4 == il) dc.x = 3.5e38f;
        if (j+5 == il) dc.y = 3.5e38f;
        if (j+6 == il) dd.x = 3.5e38f;
        if (j+7 == il) dd.y = 3.5e38f;
        float mn = fminf(fminf(fminf(da.x,da.y),fminf(db.x,db.y)),
                         fminf(fminf(dc.x,dc.y),fminf(dd.x,dd.y)));
        if (mn < kd[KG-1]){
            knn_insert(kd,ki,da.x,j);
            knn_insert(kd,ki,da.y,j+1);
            knn_insert(kd,ki,db.x,j+2);
            knn_insert(kd,ki,db.y,j+3);
            knn_insert(kd,ki,dc.x,j+4);
            knn_insert(kd,ki,dc.y,j+5);
            knn_insert(kd,ki,dd.x,j+6);
            knn_insert(kd,ki,dd.y,j+7);
        }
    }
    if (sub){
        int base = ((qg*7 + sub-1)*32 + lane)*KG;
        #pragma unroll
        for (int r=0;r<KG;r++){ mD[base+r]=kd[r]; mI[base+r]=ki[r]; }
    }
    __syncthreads();
    if (!sub){
        for (int s=0; s<7; s++){
            int base = ((qg*7 + s)*32 + lane)*KG;
            #pragma unroll
            for (int r=0;r<KG;r++) knn_insert(kd,ki, mD[base+r], mI[base+r]);
        }
        #pragma unroll
        for (int r=0;r<KG;r++) g_nbr[q*KG + r] = ki[r];
    }
}

// ---------------- grid kNN: lane=query, 2-way candidate split, 512 thr ----------
#define GRID_MERGE_N (256*KP)
#define GRID_SMEM (Nn*16 + GRID_MERGE_N*8)
__global__ void __launch_bounds__(512) k_knn_grid(const float* __restrict__ coords){
    extern __shared__ float4 sp[];
    float4* P1 = sp;
    float4* P2 = sp + 2048;
    float*  mD = (float*)(sp + 4096);
    int*    mI = (int*)(mD + GRID_MERGE_N);
    int tid = threadIdx.x, wid = tid>>5, lane = tid&31;
    int ql = (wid & 7)*32 + lane;
    int sub = wid >> 3;
    int q = blockIdx.x*256 + ql;
    int b = q / Mm;
    int m = q % Mm;
    const float* cb = coords + b*Nn*3;
    build_packed(cb, P1, P2, tid, 512);
    __syncthreads();
    float px = grid_coord( m        & 31);
    float py = grid_coord((m >> 5)  & 31);
    float pz = grid_coord( m >> 10      );
    float pp = sqsum_A(px,py,pz);
    ull ppx=pk2(px,px), ppy=pk2(py,py), ppz=pk2(pz,pz), pp2=pk2(pp,pp);
    ull n2 = pk2(-2.0f,-2.0f);
    float kd[KP]; int ki[KP];
    #pragma unroll
    for (int r=0;r<KP;r++){ kd[r]=3.4e38f; ki[r]=0; }
    const ulonglong2* U1 = (const ulonglong2*)P1;
    const ulonglong2* U2 = (const ulonglong2*)P2;
    int p0 = sub*1024;
    for (int p=p0; p<p0+1024; p+=2){
        ulonglong2 u1a = U1[p],   u2a = U2[p];
        ulonglong2 u1b = U1[p+1], u2b = U2[p+1];
        ull dpa = d2_pair(ppx,ppy,ppz,pp2,n2, u1a.x,u1a.y,u2a.x,u2a.y);
        ull dpb = d2_pair(ppx,ppy,ppz,pp2,n2, u1b.x,u1b.y,u2b.x,u2b.y);
        float2 da = upk2(dpa), db = upk2(dpb);
        float mn = fminf(fminf(da.x,da.y), fminf(db.x,db.y));
        if (mn < kd[KP-1]){
            int j = p*2;
            knn_insert(kd,ki,da.x,j);
            knn_insert(kd,ki,da.y,j+1);
            knn_insert(kd,ki,db.x,j+2);
            knn_insert(kd,ki,db.y,j+3);
        }
    }
    if (sub){
        int base = ql*KP;
        #pragma unroll
        for (int r=0;r<KP;r++){ mD[base+r]=kd[r]; mI[base+r]=ki[r]; }
    }
    __syncthreads();
    if (!sub){
        int base = ql*KP;
        #pragma unroll
        for (int r=0;r<KP;r++) knn_insert(kd,ki, mD[base+r], mI[base+r]);
        #pragma unroll
        for (int r=0;r<KP;r++){
            g_gidx[q*KP + r] = ki[r];
            g_gd2 [q*KP + r] = kd[r];
        }
    }
}

// ---------------- row GEMM ------------------------------------------------------
template<int OUT>
__global__ void k_rowgemm(const float* __restrict__ X,
                          const float* __restrict__ W,
                          const float* __restrict__ bias,
                          float* __restrict__ Y){
    __shared__ float Ws[64*OUT];
    __shared__ float xs[8][64];
    int tid = threadIdx.x;
    for (int t=tid; t<64*OUT; t+=256) Ws[t]=W[t];
    int w = tid>>5, l = tid&31;
    int r0 = blockIdx.x*8;
    for (int t=tid; t<512; t+=256) xs[t>>6][t&63] = X[(r0 + (t>>6))*64 + (t&63)];
    __syncthreads();
    int r = r0 + w;
    float acc[OUT/32];
    #pragma unroll
    for (int i=0;i<OUT/32;i++) acc[i] = bias[l + i*32];
    #pragma unroll 8
    for (int j=0;j<64;j++){
        float xj = xs[w][j];
        #pragma unroll
        for (int i=0;i<OUT/32;i++) acc[i] = fmaf(xj, Ws[j*OUT + l + i*32], acc[i]);
    }
    #pragma unroll
    for (int i=0;i<OUT/32;i++) Y[r*OUT + l + i*32] = acc[i];
}

// ---------------- GNO message passing -------------------------------------------
__global__ void k_gno_out(const float* __restrict__ coords,
                          const float* __restrict__ kW1, const float* __restrict__ kb1,
                          const float* __restrict__ kW2, const float* __restrict__ kb2,
                          int layer){
    __shared__ float W1s[96], b1s[32], W2s[32*64], b2s[64];
    __shared__ float gsh[4][KG*32];
    __shared__ float relb[4][KG][3];
    __shared__ int   ji[4][KG];
    __shared__ float psum[256];
    int tid = threadIdx.x;
    int p = tid>>6, c = tid&63;
    int pt0 = blockIdx.x*4;
    for (int t=tid; t<2048; t+=256) W2s[t]=kW2[t];
    if (tid < 96) W1s[tid]=kW1[tid];
    else if (tid < 128) b1s[tid-96]=kb1[tid-96];
    else if (tid < 192) b2s[tid-128]=kb2[tid-128];
    if (tid < 4*KG){
        int pl = tid/KG, k = tid%KG;
        int gp = pt0 + pl;
        int b = gp/Nn, i = gp%Nn;
        const float* cb = coords + b*Nn*3;
        int j = g_nbr[gp*KG + k];
        ji[pl][k] = j;
        relb[pl][k][0] = cb[j*3]  -cb[i*3];
        relb[pl][k][1] = cb[j*3+1]-cb[i*3+1];
        relb[pl][k][2] = cb[j*3+2]-cb[i*3+2];
    }
    __syncthreads();
    for (int t=tid; t<4*KG*32; t+=256){
        int pl = t/384; int rem = t - pl*384;
        int k = rem>>5, h = rem&31;
        float d = fmaf(relb[pl][k][2], W1s[64+h],
                  fmaf(relb[pl][k][1], W1s[32+h],
                  fmaf(relb[pl][k][0], W1s[h], b1s[h])));
        gsh[pl][rem] = gelu_f(d);
    }
    __syncthreads();
    int gp = pt0 + p;
    int b = gp/Nn;
    float outc = 0.0f, b2c = b2s[c];
    #pragma unroll
    for (int k=0;k<KG;k++){
        float vn = g_v[(b*Nn + ji[p][k])*GNNc + c];
        float s = b2c;
        #pragma unroll
        for (int h=0;h<32;h++) s = fmaf(gsh[p][k*32+h], W2s[h*64+c], s);
        outc = fmaf(s, vn, outc);
    }
    g_o[gp*GNNc + c] = outc;
    psum[tid] = outc;
    __syncthreads();
    if (tid < 64){
        float s = psum[tid]+psum[tid+64]+psum[tid+128]+psum[tid+192];
        atomicAdd(&g_chsumP[(layer*64 + tid)*256], s);
    }
}

__global__ void k_se(const float* __restrict__ seW1, const float* __restrict__ seW2,
                     int layer){
    __shared__ float ms[64], hs[16];
    int c = threadIdx.x;
    ms[c] = g_chsumP[(layer*64 + c)*256] * (1.0f/(float)BN);
    __syncthreads();
    if (c < 16){
        float a=0.f;
        #pragma unroll
        for (int j=0;j<64;j++) a = fmaf(ms[j], seW1[j*16+c], a);
        hs[c] = gelu_f(a);
    }
    __syncthreads();
    float a=0.f;
    #pragma unroll
    for (int h=0;h<16;h++) a = fmaf(hs[h], seW2[h*64+c], a);
    g_s[layer*64 + c] = 1.0f/(1.0f + expf(-a));
}

__global__ void k_gno_ln(const float* __restrict__ lng, const float* __restrict__ lnb,
                         int layer){
    int tid = threadIdx.x;
    int w = tid>>5, l = tid&31;
    int r = blockIdx.x*8 + w;
    float s0 = g_s[layer*64 + l], s1 = g_s[layer*64 + l+32];
    float y0 = gelu_f(fmaf(g_o[r*64+l],    s0, g_v[r*64+l]));
    float y1 = gelu_f(fmaf(g_o[r*64+l+32], s1, g_v[r*64+l+32]));
    float t1 = y0+y1, t2 = y0*y0 + y1*y1;
    #pragma unroll
    for (int off=16; off>0; off>>=1){
        t1 += __shfl_xor_sync(0xffffffffu, t1, off);
        t2 += __shfl_xor_sync(0xffffffffu, t2, off);
    }
    float mean = t1*(1.0f/64.0f);
    float var  = t2*(1.0f/64.0f) - mean*mean;
    float rs   = rsqrtf(var + 1e-5f);
    g_x[r*64+l]    = (y0-mean)*rs*lng[l]    + lnb[l];
    g_x[r*64+l+32] = (y1-mean)*rs*lng[l+32] + lnb[l+32];
}

// ============ projection v3: fp32 FFMA2 + double-buffered hs ====================
#define PF_W2   0
#define PF_HS   16384            // 2 buffers x 2048 ull = 32KB (8192 floats)
#define PF_W1   24576
#define PF_B1   24960
#define PF_B2   25088
#define PF_LG   25216
#define PF_LB   25344
#define PF_REL  25472
#define PF_WR   25856
#define PF_JI   25984
#define PROJ_FLOATS 26112
#define PROJ_SMEM (PROJ_FLOATS*4)
#define JC 32

__global__ void __launch_bounds__(256,2)
k_proj_v3(const float* __restrict__ coords,
          const float* __restrict__ W1, const float* __restrict__ b1,
          const float* __restrict__ W2, const float* __restrict__ b2,
          const float* __restrict__ lng, const float* __restrict__ lnb,
          float* __restrict__ out){
    extern __shared__ float sh[];
    float* W2s = sh + PF_W2;
    ull* hsA = (ull*)(sh + PF_HS);
    float* W1s = sh + PF_W1;
    float* b1s = sh + PF_B1;
    float* b2s = sh + PF_B2;
    float* lgs = sh + PF_LG;
    float* lbs = sh + PF_LB;
    float* relb= sh + PF_REL;
    float* wrs = sh + PF_WR;
    int*   jis = (int*)(sh + PF_JI);

    int tid = threadIdx.x, wid = tid>>5, l = tid&31;

    for (int i=tid; i<4096; i+=256) ((float4*)W2s)[i] = ((const float4*)W2)[i];
    for (int t=tid; t<384; t+=256) W1s[t]=W1[t];
    if (tid < 128){ b1s[tid]=b1[tid]; lgs[tid]=lng[tid]; }
    else { b2s[tid-128]=b2[tid-128]; lbs[tid-128]=lnb[tid-128]; }
    if (tid < 128){ b2s[tid]=b2[tid]; lbs[tid]=lnb[tid]; }
    else { b1s[tid-128]=b1[tid-128]; lgs[tid-128]=lng[tid-128]; }

    for (int tile=0; tile<NT; tile++){
        int gt = blockIdx.x*NT + tile;
        int base = gt * GPP;
        int b  = base / Mm;
        int m0 = base % Mm;
        const float* cb = coords + b*Nn*3;

        if (tid < 128){
            int gih = tid>>3, k = tid&7;
            int m = m0 + gih;
            float px = grid_coord( m        & 31);
            float py = grid_coord((m >> 5)  & 31);
            float pz = grid_coord( m >> 10      );
            long qk = (long)(b*Mm + m)*KP + k;
            int id  = g_gidx[qk];
            float d2 = g_gd2[qk];
            float dist = sqrtf(fmaxf(d2, 1e-12f));
            wrs[tid] = 1.0f/(dist + 1e-6f);
            jis[tid] = id;
            relb[tid*3+0] = px - cb[id*3];
            relb[tid*3+1] = py - cb[id*3+1];
            relb[tid*3+2] = pz - cb[id*3+2];
        }
        __syncthreads();

        ull acc[8][4];
        #pragma unroll
        for (int p=0;p<8;p++){ acc[p][0]=0; acc[p][1]=0; acc[p][2]=0; acc[p][3]=0; }
        int p0 = wid*8;

        int gp2  = tid>>2;
        int r0g = 2*gp2, r1g = 2*gp2+1;
        float a0=relb[r0g*3], a1=relb[r0g*3+1], a2=relb[r0g*3+2];
        float c0=relb[r1g*3], c1=relb[r1g*3+1], c2=relb[r1g*3+2];
        int joct = (tid&3)*8;

        #pragma unroll
        for (int jcb=0; jcb<4; jcb++){
            int jc = jcb*JC;
            ull* hs = hsA + (jcb & 1)*2048;   // double buffer: 1 sync per chunk
            #pragma unroll
            for (int u=0; u<8; u++){
                int j = jc + joct + u;
                float h0 = gelu_f(fmaf(a2, W1s[256+j], fmaf(a1, W1s[128+j], fmaf(a0, W1s[j], b1s[j]))));
                float h1 = gelu_f(fmaf(c2, W1s[256+j], fmaf(c1, W1s[128+j], fmaf(c0, W1s[j], b1s[j]))));
                hs[gp2*JC + joct + u] = pk2(h0, h1);
            }
            __syncthreads();
            #pragma unroll 4
            for (int jj=0; jj<JC; jj++){
                int j = jc + jj;
                float4 w4 = ((float4*)(W2s + j*128))[l];
                ull wx = pk2(w4.x, w4.x);
                ull wy = pk2(w4.y, w4.y);
                ull wz = pk2(w4.z, w4.z);
                ull ww = pk2(w4.w, w4.w);
                #pragma unroll
                for (int p=0;p<8;p++){
                    ull h = hs[(p0+p)*JC + jj];
                    acc[p][0] = ffma2(h, wx, acc[p][0]);
                    acc[p][1] = ffma2(h, wy, acc[p][1]);
                    acc[p][2] = ffma2(h, wz, acc[p][2]);
                    acc[p][3] = ffma2(h, ww, acc[p][3]);
                }
            }
        }

        float4 b2v = ((float4*)b2s)[l];
        float og[2][4] = {{0,0,0,0},{0,0,0,0}};
        #pragma unroll
        for (int p=0;p<8;p++){
            int r0 = wid*16 + 2*p, r1 = r0+1;
            int g = p>>2;
            float w0 = wrs[r0], w1 = wrs[r1];
            const float* pfr0 = g_pf + (long)(b*Nn + jis[r0])*LATc + 4*l;
            const float* pfr1 = g_pf + (long)(b*Nn + jis[r1])*LATc + 4*l;
            float4 pf0 = *(const float4*)pfr0;
            float4 pf1 = *(const float4*)pfr1;
            float2 v0 = upk2(acc[p][0]);
            float2 v1 = upk2(acc[p][1]);
            float2 v2 = upk2(acc[p][2]);
            float2 v3 = upk2(acc[p][3]);
            og[g][0] = fmaf((v0.x+b2v.x)*w0, pf0.x, fmaf((v0.y+b2v.x)*w1, pf1.x, og[g][0]));
            og[g][1] = fmaf((v1.x+b2v.y)*w0, pf0.y, fmaf((v1.y+b2v.y)*w1, pf1.y, og[g][1]));
            og[g][2] = fmaf((v2.x+b2v.z)*w0, pf0.z, fmaf((v2.y+b2v.z)*w1, pf1.z, og[g][2]));
            og[g][3] = fmaf((v3.x+b2v.w)*w0, pf0.w, fmaf((v3.y+b2v.w)*w1, pf1.w, og[g][3]));
        }

        #pragma unroll
        for (int g=0; g<2; g++){
            int gi = 2*wid + g;
            float ws = 0.f;
            #pragma unroll
            for (int k=0;k<KP;k++) ws += wrs[gi*8+k];
            float inv = 1.0f/ws;
            float o0 = og[g][0]*inv, o1 = og[g][1]*inv, o2 = og[g][2]*inv, o3 = og[g][3]*inv;
            float s1 = o0+o1+o2+o3;
            float s2 = o0*o0+o1*o1+o2*o2+o3*o3;
            #pragma unroll
            for (int off=16; off>0; off>>=1){
                s1 += __shfl_xor_sync(0xffffffffu, s1, off);
                s2 += __shfl_xor_sync(0xffffffffu, s2, off);
            }
            float mean = s1*(1.0f/128.0f);
            float var  = s2*(1.0f/128.0f) - mean*mean;
            float rs   = rsqrtf(var + 1e-5f);
            long obase = ((long)b*128)*Mm + m0 + gi;
            int c = 4*l;
            out[obase + (long)(c  )*Mm] = (o0-mean)*rs*lgs[c  ] + lbs[c  ];
            out[obase + (long)(c+1)*Mm] = (o1-mean)*rs*lgs[c+1] + lbs[c+1];
            out[obase + (long)(c+2)*Mm] = (o2-mean)*rs*lgs[c+2] + lbs[c+2];
            out[obase + (long)(c+3)*Mm] = (o3-mean)*rs*lgs[c+3] + lbs[c+3];
        }
        __syncthreads();
    }
}

// ---------------- launcher -------------------------------------------------------
extern "C" void kernel_launch(void* const* d_in, const int* in_sizes, int n_in,
                              void* d_out, int out_size){
    const float* coords = (const float*)d_in[0];
    const float* feats  = (const float*)d_in[1];
    const float* W_in   = (const float*)d_in[2];
    const float* b_in   = (const float*)d_in[3];
    const float* W_lat  = (const float*)d_in[24];
    const float* b_lat  = (const float*)d_in[25];
    const float* p_kW1  = (const float*)d_in[26];
    const float* p_kb1  = (const float*)d_in[27];
    const float* p_kW2  = (const float*)d_in[28];
    const float* p_kb2  = (const float*)d_in[29];
    const float* p_lng  = (const float*)d_in[30];
    const float* p_lnb  = (const float*)d_in[31];

    cudaFuncSetAttribute(k_knn_self, cudaFuncAttributeMaxDynamicSharedMemorySize, SELF_SMEM);
    cudaFuncSetAttribute(k_knn_grid, cudaFuncAttributeMaxDynamicSharedMemorySize, GRID_SMEM);
    cudaFuncSetAttribute(k_proj_v3,  cudaFuncAttributeMaxDynamicSharedMemorySize, PROJ_SMEM);

    float* xg; cudaGetSymbolAddress((void**)&xg, g_x);
    float* vg; cudaGetSymbolAddress((void**)&vg, g_v);
    float* pfg; cudaGetSymbolAddress((void**)&pfg, g_pf);

    // slot 4 of ncu sampling = k_knn_self (last unmeasured kernel)
    k_input<<<(BN*GNNc)/256, 256>>>(feats, W_in, b_in);
    k_rowgemm<64><<<BN/8, 256>>>(xg, (const float*)d_in[8], (const float*)d_in[9], vg);
    k_knn_grid<<<BM/256, 512, GRID_SMEM>>>(coords);
    k_knn_self<<<BN/64, 512, SELF_SMEM>>>(coords);

    for (int layer = 0; layer < 2; layer++){
        int base = 4 + layer*10;
        const float* kW1  = (const float*)d_in[base+0];
        const float* kb1  = (const float*)d_in[base+1];
        const float* kW2  = (const float*)d_in[base+2];
        const float* kb2  = (const float*)d_in[base+3];
        const float* vW   = (const float*)d_in[base+4];
        const float* vb   = (const float*)d_in[base+5];
        const float* lng  = (const float*)d_in[base+6];
        const float* lnb  = (const float*)d_in[base+7];
        const float* seW1 = (const float*)d_in[base+8];
        const float* seW2 = (const float*)d_in[base+9];

        if (layer == 1)
            k_rowgemm<64><<<BN/8, 256>>>(xg, vW, vb, vg);
        k_gno_out<<<BN/4, 256>>>(coords, kW1, kb1, kW2, kb2, layer);
        k_se<<<1, 64>>>(seW1, seW2, layer);
        k_gno_ln<<<BN/8, 256>>>(lng, lnb, layer);
    }

    k_rowgemm<128><<<BN/8, 256>>>(xg, W_lat, b_lat, pfg);
    k_proj_v3<<<PROJ_GRID, 256, PROJ_SMEM>>>(coords, p_kW1, p_kb1, p_kW2, p_kb2,
                                             p_lng, p_lnb, (float*)d_out);
}